// round 1
// baseline (speedup 1.0000x reference)
#include <cuda_runtime.h>
#include <cuda_fp16.h>
#include <cstdint>

// Problem: y[b,s,o] = sum_i x[b,s,i] * (q[o,i]-zp[o])*scale[o] + bias[o]
//   =>  y[m,o] = scale[o]*( dot(x[m],q[o]) - zp[o]*rowsum(x[m]) ) + bias[o]
// q in [0,255] is EXACT in fp16 -> fp16 tensor-core GEMM, fp32 accumulate.

static constexpr int M_TOTAL = 8192;    // 4*2048
static constexpr int K_TOTAL = 4096;
static constexpr int N_TOTAL = 11008;

static constexpr int BM = 128, BN = 128, BK = 64;
static constexpr int KTILES = K_TOTAL / BK;  // 64

// Scratch (static __device__ arrays: allocation-free per harness rules)
__device__ __half g_Xh[(size_t)M_TOTAL * K_TOTAL];   // x in fp16
__device__ __half g_Wh[(size_t)N_TOTAL * K_TOTAL];   // q codes in fp16 (exact)
__device__ float  g_rowsum[M_TOTAL];                 // per-row sum of x (fp32)

// ---------------------------------------------------------------------------
// helpers
// ---------------------------------------------------------------------------
__device__ __forceinline__ int swz(int row, int chunk) {
    // 128B rows (64 halves), 8 chunks of 16B, xor-swizzle for conflict-free
    // ldmatrix and cp.async stores.
    return row * BK + ((chunk ^ (row & 7)) << 3);
}

__device__ __forceinline__ void cp_async16(void* s, const void* g) {
    uint32_t sa = (uint32_t)__cvta_generic_to_shared(s);
    asm volatile("cp.async.cg.shared.global [%0], [%1], 16;" :: "r"(sa), "l"(g));
}
__device__ __forceinline__ void cp_commit() { asm volatile("cp.async.commit_group;"); }
__device__ __forceinline__ void cp_wait0()  { asm volatile("cp.async.wait_group 0;"); }

__device__ __forceinline__ void ldm_x4(uint32_t* r, const __half* p) {
    uint32_t sa = (uint32_t)__cvta_generic_to_shared(p);
    asm volatile("ldmatrix.sync.aligned.m8n8.x4.shared.b16 {%0,%1,%2,%3}, [%4];"
                 : "=r"(r[0]), "=r"(r[1]), "=r"(r[2]), "=r"(r[3]) : "r"(sa));
}

__device__ __forceinline__ void mma16816(float* c, const uint32_t* a, const uint32_t* b) {
    asm volatile(
        "mma.sync.aligned.m16n8k16.row.col.f32.f16.f16.f32 "
        "{%0,%1,%2,%3}, {%4,%5,%6,%7}, {%8,%9}, {%0,%1,%2,%3};"
        : "+f"(c[0]), "+f"(c[1]), "+f"(c[2]), "+f"(c[3])
        : "r"(a[0]), "r"(a[1]), "r"(a[2]), "r"(a[3]), "r"(b[0]), "r"(b[1]));
}

// ---------------------------------------------------------------------------
// conversion kernels (run every launch; deterministic)
// ---------------------------------------------------------------------------
__global__ void convert_x_kernel(const float* __restrict__ x) {
    const int row = blockIdx.x;
    const float* xr = x + (size_t)row * K_TOTAL;
    __half* xo = g_Xh + (size_t)row * K_TOTAL;
    float s = 0.f;
    for (int i = threadIdx.x * 4; i < K_TOTAL; i += blockDim.x * 4) {
        float4 v = *(const float4*)(xr + i);
        s += v.x + v.y + v.z + v.w;
        *(__half2*)(xo + i)     = __floats2half2_rn(v.x, v.y);
        *(__half2*)(xo + i + 2) = __floats2half2_rn(v.z, v.w);
    }
    #pragma unroll
    for (int off = 16; off; off >>= 1) s += __shfl_down_sync(~0u, s, off);
    __shared__ float ws[8];
    if ((threadIdx.x & 31) == 0) ws[threadIdx.x >> 5] = s;
    __syncthreads();
    if (threadIdx.x < 8) {
        float v = ws[threadIdx.x];
        #pragma unroll
        for (int off = 4; off; off >>= 1) v += __shfl_down_sync(0xffu, v, off);
        if (threadIdx.x == 0) g_rowsum[row] = v;
    }
}

__global__ void convert_w_kernel(const int* __restrict__ q) {
    const size_t total4 = (size_t)N_TOTAL * K_TOTAL / 4;
    for (size_t i = (size_t)blockIdx.x * blockDim.x + threadIdx.x; i < total4;
         i += (size_t)gridDim.x * blockDim.x) {
        int4 v = ((const int4*)q)[i];
        __half2* o = (__half2*)(g_Wh + i * 4);
        o[0] = __halves2half2(__int2half_rn(v.x), __int2half_rn(v.y));
        o[1] = __halves2half2(__int2half_rn(v.z), __int2half_rn(v.w));
    }
}

// ---------------------------------------------------------------------------
// GEMM: 128x128x64 block tile, 8 warps (4m x 2n), warp tile 32x64,
// mma.m16n8k16 fp16->fp32, cp.async double buffering, swizzled smem.
// ---------------------------------------------------------------------------
__global__ void __launch_bounds__(256) woq_gemm_kernel(
    const float* __restrict__ scales, const float* __restrict__ zps,
    const float* __restrict__ bias, float* __restrict__ out)
{
    extern __shared__ __half smem[];
    __half* sA = smem;                 // [2][BM][BK]
    __half* sB = smem + 2 * BM * BK;   // [2][BN][BK]

    const int tid  = threadIdx.x;
    const int lane = tid & 31;
    const int warp = tid >> 5;
    const int wm = warp & 3;   // 0..3  -> 32 rows each
    const int wn = warp >> 2;  // 0..1  -> 64 cols each

    const int bm = blockIdx.y * BM;
    const int bn = blockIdx.x * BN;

    // global -> smem loaders: thread t loads row t/8, 16B chunk t%8, 4 passes
    const int lrow   = tid >> 3;   // 0..31
    const int lchunk = tid & 7;    // 0..7
    const __half* gA = g_Xh + (size_t)(bm + lrow) * K_TOTAL + lchunk * 8;
    const __half* gB = g_Wh + (size_t)(bn + lrow) * K_TOTAL + lchunk * 8;

    float c[2][8][4];
    #pragma unroll
    for (int i = 0; i < 2; i++)
        #pragma unroll
        for (int j = 0; j < 8; j++)
            #pragma unroll
            for (int k = 0; k < 4; k++) c[i][j][k] = 0.f;

    // ldmatrix lane addressing (A: 16x16 x4; B: two 8-wide n tiles x4)
    const int mat = lane >> 3;
    const int arow0  = wm * 32 + (mat & 1) * 8 + (lane & 7);  // + mi*16
    const int achunk = mat >> 1;                              // + k0/8
    const int brow0  = wn * 64 + ((mat >> 1) << 3) + (lane & 7); // + nj*16
    const int bchunk = mat & 1;                               // + k0/8

    auto load_tile = [&](int stage, int kt) {
        const __half* ga = gA + kt * BK;
        const __half* gb = gB + kt * BK;
        __half* sa = sA + stage * BM * BK;
        __half* sb = sB + stage * BN * BK;
        #pragma unroll
        for (int r = 0; r < BM; r += 32) {
            cp_async16(sa + swz(lrow + r, lchunk), ga + (size_t)r * K_TOTAL);
            cp_async16(sb + swz(lrow + r, lchunk), gb + (size_t)r * K_TOTAL);
        }
        cp_commit();
    };

    load_tile(0, 0);
    cp_wait0();
    __syncthreads();

    for (int kt = 0; kt < KTILES; kt++) {
        const int cur = kt & 1;
        if (kt + 1 < KTILES) load_tile(cur ^ 1, kt + 1);

        const __half* sa = sA + cur * BM * BK;
        const __half* sb = sB + cur * BN * BK;

        #pragma unroll
        for (int kk = 0; kk < 4; kk++) {
            const int kc = kk << 1;  // k0/8
            uint32_t a[2][4];
            #pragma unroll
            for (int mi = 0; mi < 2; mi++)
                ldm_x4(a[mi], sa + swz(arow0 + mi * 16, kc + achunk));
            uint32_t b[8][2];
            #pragma unroll
            for (int nj = 0; nj < 4; nj++) {
                uint32_t t[4];
                ldm_x4(t, sb + swz(brow0 + nj * 16, kc + bchunk));
                b[nj*2  ][0] = t[0]; b[nj*2  ][1] = t[1];
                b[nj*2+1][0] = t[2]; b[nj*2+1][1] = t[3];
            }
            #pragma unroll
            for (int mi = 0; mi < 2; mi++)
                #pragma unroll
                for (int nt = 0; nt < 8; nt++)
                    mma16816(c[mi][nt], a[mi], b[nt]);
        }
        cp_wait0();
        __syncthreads();
    }

    // epilogue: y = s*(acc - zp*rowsum) + bias
    const int er = lane >> 2;        // row within 8
    const int ec = (lane & 3) * 2;   // col pair within 8

    float rs[2][2];
    #pragma unroll
    for (int mi = 0; mi < 2; mi++)
        #pragma unroll
        for (int h = 0; h < 2; h++)
            rs[mi][h] = g_rowsum[bm + wm*32 + mi*16 + h*8 + er];

    #pragma unroll
    for (int nt = 0; nt < 8; nt++) {
        const int gn = bn + wn*64 + nt*8 + ec;
        const float s0 = scales[gn],  s1 = scales[gn+1];
        const float z0 = zps[gn],     z1 = zps[gn+1];
        const float b0 = bias[gn],    b1 = bias[gn+1];
        #pragma unroll
        for (int mi = 0; mi < 2; mi++) {
            #pragma unroll
            for (int h = 0; h < 2; h++) {
                const int gm = bm + wm*32 + mi*16 + h*8 + er;
                float2 v;
                v.x = s0 * (c[mi][nt][h*2+0] - z0 * rs[mi][h]) + b0;
                v.y = s1 * (c[mi][nt][h*2+1] - z1 * rs[mi][h]) + b1;
                *(float2*)(out + (size_t)gm * N_TOTAL + gn) = v;
            }
        }
    }
}

// ---------------------------------------------------------------------------
extern "C" void kernel_launch(void* const* d_in, const int* in_sizes, int n_in,
                              void* d_out, int out_size) {
    const float* x  = (const float*)d_in[0];
    const int*   qw = (const int*)d_in[1];
    const float* sc = (const float*)d_in[2];
    const float* zp = (const float*)d_in[3];
    const float* bi = (const float*)d_in[4];
    float* out = (float*)d_out;

    convert_x_kernel<<<M_TOTAL, 256>>>(x);
    convert_w_kernel<<<8192, 256>>>(qw);

    const int smem_bytes = 2 * (BM + BN) * BK * (int)sizeof(__half);  // 64 KB
    cudaFuncSetAttribute(woq_gemm_kernel,
                         cudaFuncAttributeMaxDynamicSharedMemorySize, smem_bytes);
    dim3 grid(N_TOTAL / BN, M_TOTAL / BM);  // (86, 64), exact fit: no bounds checks
    woq_gemm_kernel<<<grid, 256, smem_bytes>>>(sc, zp, bi, out);
}